// round 16
// baseline (speedup 1.0000x reference)
#include <cuda_runtime.h>
#include <cuda_bf16.h>
#include <math.h>
#include <stdint.h>

// Problem constants
#define PB 8
#define PL 256
#define PD 2048
#define PH 8
#define PDH 256
#define PT (PB*PL)
#define BH (PB*PH)

// ---------------- scratch ----------------
__device__ float g_o[PT*PD];
__device__ float g_mh[PH*PL];

__device__ __nv_bfloat16 g_qproj[BH*PL*PDH];
__device__ __nv_bfloat16 g_kvbf[BH*PL*PL];
__device__ __nv_bfloat16 g_kbhl[BH*PL*PDH];
__device__ __nv_bfloat16 g_vbhl[BH*PL*PDH];
__device__ __nv_bfloat16 g_vt[BH*PDH*PL];
__device__ __nv_bfloat16 g_pk[BH*PL*PDH];
__device__ __nv_bfloat16 g_attnbf[PT*PD];

__device__ __nv_bfloat16 g_qbf[PT*PD];
__device__ __nv_bfloat16 g_kbf[PT*PD];
__device__ __nv_bfloat16 g_vbf[PT*PD];
__device__ __nv_bfloat16 g_wqbf[PD*PD];
__device__ __nv_bfloat16 g_wkbf[PD*PD];
__device__ __nv_bfloat16 g_wvbf[PD*PD];
__device__ __nv_bfloat16 g_wobf[PD*PD];

// ---------------- helpers ----------------
__device__ __forceinline__ uint32_t f2bf2(float lo, float hi) {
    __nv_bfloat162 h = __float22bfloat162_rn(make_float2(lo, hi));
    return *(uint32_t*)&h;
}
__device__ __forceinline__ float2 bf2f(uint32_t r) {
    return __bfloat1622float2(*(__nv_bfloat162*)&r);
}
__device__ __forceinline__ float phif(float x) {
    return x > 0.f ? x + 1.f : __expf(x);
}
__device__ __forceinline__ uint32_t smem_u32(const void* p) {
    uint32_t a;
    asm("{ .reg .u64 t; cvta.to.shared.u64 t, %1; cvt.u32.u64 %0, t; }" : "=r"(a) : "l"(p));
    return a;
}
#define CP_ASYNC16(dst, src) \
    asm volatile("cp.async.cg.shared.global [%0], [%1], 16;" :: "r"(dst), "l"(src))
#define CP_COMMIT() asm volatile("cp.async.commit_group;")
#define LDSM4(r0, r1, r2, r3, a) \
    asm volatile("ldmatrix.sync.aligned.m8n8.x4.shared.b16 {%0,%1,%2,%3}, [%4];" \
        : "=r"(r0), "=r"(r1), "=r"(r2), "=r"(r3) : "r"(a))
#define MMA_BF16(acc, af, bfr) \
    asm volatile( \
        "mma.sync.aligned.m16n8k16.row.col.f32.bf16.bf16.f32 " \
        "{%0,%1,%2,%3}, {%4,%5,%6,%7}, {%8,%9}, {%0,%1,%2,%3};\n" \
        : "+f"((acc)[0]), "+f"((acc)[1]), "+f"((acc)[2]), "+f"((acc)[3]) \
        : "r"((af)[0]), "r"((af)[1]), "r"((af)[2]), "r"((af)[3]), \
          "r"((bfr)[0]), "r"((bfr)[1]))

#define PSTR 20

// ================= merged fp32->bf16 conversions + mh zero =================
struct CvtArgs {
    const float* src[7];
    __nv_bfloat16* dst[7];
    float* mh;
};

__global__ void cvt_all_kernel(CvtArgs a) {
    if (blockIdx.x >= 7168) {
        for (int j = threadIdx.x; j < PH*PL; j += 256) a.mh[j] = 0.f;
        return;
    }
    const int job = blockIdx.x >> 10;
    const long blk = blockIdx.x & 1023;
    const float* __restrict__ src = a.src[job];
    __nv_bfloat16* __restrict__ dst = a.dst[job];
    const long i = (blk * 256 + threadIdx.x) * 16;
    const float4 v0 = *(const float4*)(src + i);
    const float4 v1 = *(const float4*)(src + i + 4);
    const float4 v2 = *(const float4*)(src + i + 8);
    const float4 v3 = *(const float4*)(src + i + 12);
    uint4 p0, p1;
    p0.x = f2bf2(v0.x, v0.y); p0.y = f2bf2(v0.z, v0.w);
    p0.z = f2bf2(v1.x, v1.y); p0.w = f2bf2(v1.z, v1.w);
    p1.x = f2bf2(v2.x, v2.y); p1.y = f2bf2(v2.z, v2.w);
    p1.z = f2bf2(v3.x, v3.y); p1.w = f2bf2(v3.z, v3.w);
    *(uint4*)(dst + i) = p0;
    *(uint4*)(dst + i + 8) = p1;
}

// ================= big bf16 GEMM core (256x128 tile, 512 threads) =================
#define STGA (256*PSTR)
#define STGB (128*PSTR)
#define NSTB 6
#define BIG_SMEM (NSTB*(STGA + STGB)*4)

__global__ __launch_bounds__(512, 1)
void big3_gemm(const __nv_bfloat16* __restrict__ qbf, const __nv_bfloat16* __restrict__ kbf,
               const __nv_bfloat16* __restrict__ vbf,
               const __nv_bfloat16* __restrict__ wq, const __nv_bfloat16* __restrict__ wk,
               const __nv_bfloat16* __restrict__ wv,
               __nv_bfloat16* __restrict__ Qo, __nv_bfloat16* __restrict__ kbhl,
               __nv_bfloat16* __restrict__ pk, __nv_bfloat16* __restrict__ vbhl)
{
    extern __shared__ __align__(16) uint32_t sm[];
    const uint32_t sbase = smem_u32(sm);

    const int z = blockIdx.z;
    const __nv_bfloat16* __restrict__ Ag = (z == 0) ? qbf : (z == 1) ? kbf : vbf;
    const __nv_bfloat16* __restrict__ Wg = (z == 0) ? wq  : (z == 1) ? wk  : wv;

    const int tid = threadIdx.x;
    const int lane = tid & 31;
    const int warpId = tid >> 5;
    const int g = lane >> 2;
    const int t = lane & 3;
    const int warpM = warpId >> 2;
    const int warpN = warpId & 3;
    const int m0 = blockIdx.y * 256;
    const int n0 = blockIdx.x * 128;

    const int ga0 = tid, ga1 = tid + 512;
    const int ar0 = ga0 >> 2, ac0 = ga0 & 3;
    const int ar1 = ga1 >> 2, ac1 = ga1 & 3;
    const int br  = tid >> 2, bc = tid & 3;
    const uint32_t da0 = (ar0 * PSTR + ac0 * 4) * 4;
    const uint32_t da1 = (ar1 * PSTR + ac1 * 4) * 4;
    const uint32_t db  = (br  * PSTR + bc  * 4) * 4;

    uint32_t aoff[4];
#pragma unroll
    for (int mt = 0; mt < 4; mt++) {
        const int ar = warpM * 64 + mt * 16 + (lane & 15);
        const int ac = (lane >> 4) * 4;
        aoff[mt] = (ar * PSTR + ac) * 4;
    }
    uint32_t boff[2];
#pragma unroll
    for (int p = 0; p < 2; p++) {
        const int brr = warpN * 32 + p * 16 + (lane & 7) + ((lane >> 4) << 3);
        const int bcc = ((lane >> 3) & 1) * 4;
        boff[p] = (brr * PSTR + bcc) * 4;
    }

    float acc[4][4][4];
#pragma unroll
    for (int mt = 0; mt < 4; mt++)
#pragma unroll
        for (int nt = 0; nt < 4; nt++)
#pragma unroll
            for (int i = 0; i < 4; i++) acc[mt][nt][i] = 0.f;

    auto issue = [&](int s) {
        const int st = s % NSTB;
        const uint32_t aT = sbase + st * STGA * 4;
        const uint32_t bT = sbase + (NSTB * STGA + st * STGB) * 4;
        const int k0 = s * 32;
        CP_ASYNC16(aT + da0, Ag + (long)(m0 + ar0) * PD + k0 + ac0 * 8);
        CP_ASYNC16(aT + da1, Ag + (long)(m0 + ar1) * PD + k0 + ac1 * 8);
        CP_ASYNC16(bT + db,  Wg + (long)(n0 + br)  * PD + k0 + bc  * 8);
        CP_COMMIT();
    };

    const int NSTAGE = PD / 32;
    issue(0); issue(1); issue(2);

    for (int s = 0; s < NSTAGE; s++) {
        if (s + 3 < NSTAGE) { issue(s + 3); asm volatile("cp.async.wait_group 3;"); }
        else if (s + 2 < NSTAGE) { asm volatile("cp.async.wait_group 2;"); }
        else if (s + 1 < NSTAGE) { asm volatile("cp.async.wait_group 1;"); }
        else { asm volatile("cp.async.wait_group 0;"); }
        __syncthreads();

        const int st = s % NSTB;
        const uint32_t aT = sbase + st * STGA * 4;
        const uint32_t bT = sbase + (NSTB * STGA + st * STGB) * 4;

#pragma unroll
        for (int kk = 0; kk < 16; kk += 8) {
            uint32_t af[4][4];
#pragma unroll
            for (int mt = 0; mt < 4; mt++)
                LDSM4(af[mt][0], af[mt][1], af[mt][2], af[mt][3], aT + aoff[mt] + kk * 4);
            uint32_t bfr[4][2];
#pragma unroll
            for (int p = 0; p < 2; p++)
                LDSM4(bfr[2*p][0], bfr[2*p][1], bfr[2*p+1][0], bfr[2*p+1][1],
                      bT + boff[p] + kk * 4);
#pragma unroll
            for (int mt = 0; mt < 4; mt++)
#pragma unroll
                for (int nt = 0; nt < 4; nt++)
                    MMA_BF16(acc[mt][nt], af[mt], bfr[nt]);
        }
    }

#pragma unroll
    for (int mt = 0; mt < 4; mt++) {
        const int rL = m0 + warpM*64 + mt*16 + g;
        const int rH = rL + 8;
#pragma unroll
        for (int nt = 0; nt < 4; nt++) {
            const int c = n0 + warpN*32 + nt*8 + t*2;
            float2 vL = make_float2(acc[mt][nt][0], acc[mt][nt][1]);
            float2 vH = make_float2(acc[mt][nt][2], acc[mt][nt][3]);
            const int h = c >> 8, d = c & 255;
            const int bL = rL >> 8, lL = rL & 255;
            const int bR = rH >> 8, lH = rH & 255;
            const long iL = (((long)(bL*PH + h))*PL + lL)*PDH + d;
            const long iH = (((long)(bR*PH + h))*PL + lH)*PDH + d;
            if (z == 0) {
                ((uint32_t*)Qo)[iL >> 1] = f2bf2(vL.x, vL.y);
                ((uint32_t*)Qo)[iH >> 1] = f2bf2(vH.x, vH.y);
            } else if (z == 1) {
                ((uint32_t*)kbhl)[iL >> 1] = f2bf2(vL.x, vL.y);
                ((uint32_t*)kbhl)[iH >> 1] = f2bf2(vH.x, vH.y);
                ((uint32_t*)pk)[iL >> 1] = f2bf2(phif(vL.x), phif(vL.y));
                ((uint32_t*)pk)[iH >> 1] = f2bf2(phif(vH.x), phif(vH.y));
            } else {
                ((uint32_t*)vbhl)[iL >> 1] = f2bf2(vL.x, vL.y);
                ((uint32_t*)vbhl)[iH >> 1] = f2bf2(vH.x, vH.y);
            }
        }
    }
}

__global__ __launch_bounds__(512, 1)
void bigo_gemm(const __nv_bfloat16* __restrict__ Ag, const __nv_bfloat16* __restrict__ Wg,
               float* __restrict__ Cg, const float* __restrict__ bias)
{
    extern __shared__ __align__(16) uint32_t sm[];
    const uint32_t sbase = smem_u32(sm);

    const int tid = threadIdx.x;
    const int lane = tid & 31;
    const int warpId = tid >> 5;
    const int g = lane >> 2;
    const int t = lane & 3;
    const int warpM = warpId >> 2;
    const int warpN = warpId & 3;
    const int m0 = blockIdx.y * 256;
    const int n0 = blockIdx.x * 128;

    const int ga0 = tid, ga1 = tid + 512;
    const int ar0 = ga0 >> 2, ac0 = ga0 & 3;
    const int ar1 = ga1 >> 2, ac1 = ga1 & 3;
    const int br  = tid >> 2, bc = tid & 3;
    const uint32_t da0 = (ar0 * PSTR + ac0 * 4) * 4;
    const uint32_t da1 = (ar1 * PSTR + ac1 * 4) * 4;
    const uint32_t db  = (br  * PSTR + bc  * 4) * 4;

    uint32_t aoff[4];
#pragma unroll
    for (int mt = 0; mt < 4; mt++) {
        const int ar = warpM * 64 + mt * 16 + (lane & 15);
        const int ac = (lane >> 4) * 4;
        aoff[mt] = (ar * PSTR + ac) * 4;
    }
    uint32_t boff[2];
#pragma unroll
    for (int p = 0; p < 2; p++) {
        const int brr = warpN * 32 + p * 16 + (lane & 7) + ((lane >> 4) << 3);
        const int bcc = ((lane >> 3) & 1) * 4;
        boff[p] = (brr * PSTR + bcc) * 4;
    }

    float acc[4][4][4];
#pragma unroll
    for (int mt = 0; mt < 4; mt++)
#pragma unroll
        for (int nt = 0; nt < 4; nt++)
#pragma unroll
            for (int i = 0; i < 4; i++) acc[mt][nt][i] = 0.f;

    auto issue = [&](int s) {
        const int st = s % NSTB;
        const uint32_t aT = sbase + st * STGA * 4;
        const uint32_t bT = sbase + (NSTB * STGA + st * STGB) * 4;
        const int k0 = s * 32;
        CP_ASYNC16(aT + da0, Ag + (long)(m0 + ar0) * PD + k0 + ac0 * 8);
        CP_ASYNC16(aT + da1, Ag + (long)(m0 + ar1) * PD + k0 + ac1 * 8);
        CP_ASYNC16(bT + db,  Wg + (long)(n0 + br)  * PD + k0 + bc  * 8);
        CP_COMMIT();
    };

    const int NSTAGE = PD / 32;
    issue(0); issue(1); issue(2);

    for (int s = 0; s < NSTAGE; s++) {
        if (s + 3 < NSTAGE) { issue(s + 3); asm volatile("cp.async.wait_group 3;"); }
        else if (s + 2 < NSTAGE) { asm volatile("cp.async.wait_group 2;"); }
        else if (s + 1 < NSTAGE) { asm volatile("cp.async.wait_group 1;"); }
        else { asm volatile("cp.async.wait_group 0;"); }
        __syncthreads();

        const int st = s % NSTB;
        const uint32_t aT = sbase + st * STGA * 4;
        const uint32_t bT = sbase + (NSTB * STGA + st * STGB) * 4;

#pragma unroll
        for (int kk = 0; kk < 16; kk += 8) {
            uint32_t af[4][4];
#pragma unroll
            for (int mt = 0; mt < 4; mt++)
                LDSM4(af[mt][0], af[mt][1], af[mt][2], af[mt][3], aT + aoff[mt] + kk * 4);
            uint32_t bfr[4][2];
#pragma unroll
            for (int p = 0; p < 2; p++)
                LDSM4(bfr[2*p][0], bfr[2*p][1], bfr[2*p+1][0], bfr[2*p+1][1],
                      bT + boff[p] + kk * 4);
#pragma unroll
            for (int mt = 0; mt < 4; mt++)
#pragma unroll
                for (int nt = 0; nt < 4; nt++)
                    MMA_BF16(acc[mt][nt], af[mt], bfr[nt]);
        }
    }

#pragma unroll
    for (int mt = 0; mt < 4; mt++) {
        const int rL = m0 + warpM*64 + mt*16 + g;
        const int rH = rL + 8;
#pragma unroll
        for (int nt = 0; nt < 4; nt++) {
            const int c = n0 + warpN*32 + nt*8 + t*2;
            float2 bv = *(const float2*)&bias[c];
            *(float2*)&Cg[(long)rL*PD + c] = make_float2(acc[mt][nt][0] + bv.x, acc[mt][nt][1] + bv.y);
            *(float2*)&Cg[(long)rH*PD + c] = make_float2(acc[mt][nt][2] + bv.x, acc[mt][nt][3] + bv.y);
        }
    }
}

// ================= kv GEMM + parallel V^T (merged launch) =================
// grid (2, 2, 96): z < 64 -> kv GEMM blocks (xy tile); z in [64,96) -> V^T blocks.
#define BSTG (128*PSTR)
#define NSTS 4
#define BAT_SMEM (2*NSTS*BSTG*4)

__global__ __launch_bounds__(256, 2)
void kv_vt_kernel(const __nv_bfloat16* __restrict__ Ag, const __nv_bfloat16* __restrict__ Bg,
                  __nv_bfloat16* __restrict__ Cg, float* __restrict__ mhp,
                  __nv_bfloat16* __restrict__ vtg)
{
    extern __shared__ __align__(16) uint32_t sm[];
    const uint32_t sbase = smem_u32(sm);
    __shared__ float colsum[128];
    __shared__ __nv_bfloat16 ttile[32][33];

    const int tid = threadIdx.x;

    if (blockIdx.z >= 64) {
        // ---- V^T blocks: 128 CTAs, each transposes 32 of the 4096 32x32 tiles ----
        const int idx = (blockIdx.z - 64) * 4 + blockIdx.y * 2 + blockIdx.x;  // 0..127
        const int tx = tid & 31;
        const int ty = tid >> 5;   // 0..7
        for (int it = 0; it < 32; it++) {
            const int tile = idx * 32 + it;       // 0..4095
            const int zz  = tile >> 6;            // head 0..63
            const int rem = tile & 63;
            const int l0 = (rem & 7) * 32;
            const int d0 = (rem >> 3) * 32;
            const __nv_bfloat16* src = Bg + (long)zz * PL * PDH;
            __nv_bfloat16* dst = vtg + (long)zz * PDH * PL;
            __syncthreads();
#pragma unroll
            for (int j = 0; j < 4; j++)
                ttile[ty*4 + j][tx] = src[(long)(l0 + ty*4 + j) * PDH + d0 + tx];
            __syncthreads();
#pragma unroll
            for (int j = 0; j < 4; j++)
                dst[(long)(d0 + ty*4 + j) * PL + l0 + tx] = ttile[tx][ty*4 + j];
        }
        return;
    }

    // ---- kv GEMM blocks (unchanged R13 form) ----
    const int lane = tid & 31;
    const int warpId = tid >> 5;
    const int g = lane >> 2;
    const int t = lane & 3;
    const int warpM = warpId >> 2;
    const int warpN = warpId & 3;
    const int m0 = blockIdx.y * 128;
    const int n0 = blockIdx.x * 128;
    const int z  = blockIdx.z;
    const __nv_bfloat16* A  = Ag + (long)z * PL * PDH;
    const __nv_bfloat16* Bm = Bg + (long)z * PL * PDH;

    if (tid < 128) colsum[tid] = 0.f;

    const int gid0 = tid, gid1 = tid + 256;
    const int row0 = gid0 >> 2, gc0 = gid0 & 3;
    const int row1 = gid1 >> 2, gc1 = gid1 & 3;
    const uint32_t d0 = (row0 * PSTR + gc0 * 4) * 4;
    const uint32_t d1 = (row1 * PSTR + gc1 * 4) * 4;

    uint32_t aoff[4];
#pragma unroll
    for (int mt = 0; mt < 4; mt++) {
        const int ar = warpM * 64 + mt * 16 + (lane & 15);
        const int ac = (lane >> 4) * 4;
        aoff[mt] = (ar * PSTR + ac) * 4;
    }
    uint32_t boff[2];
#pragma unroll
    for (int p = 0; p < 2; p++) {
        const int br = warpN * 32 + p * 16 + (lane & 7) + ((lane >> 4) << 3);
        const int bc = ((lane >> 3) & 1) * 4;
        boff[p] = (br * PSTR + bc) * 4;
    }

    float acc[4][4][4];
#pragma unroll
    for (int mt = 0; mt < 4; mt++)
#pragma unroll
        for (int nt = 0; nt < 4; nt++)
#pragma unroll
            for (int i = 0; i < 4; i++) acc[mt][nt][i] = 0.f;

    auto issue = [&](int s) {
        const int st = s & (NSTS - 1);
        const uint32_t aT = sbase + st * BSTG * 4;
        const uint32_t bT = sbase + (NSTS + st) * BSTG * 4;
        const int k0 = s * 32;
        CP_ASYNC16(aT + d0, A  + (long)(m0 + row0) * PDH + k0 + gc0 * 8);
        CP_ASYNC16(aT + d1, A  + (long)(m0 + row1) * PDH + k0 + gc1 * 8);
        CP_ASYNC16(bT + d0, Bm + (long)(n0 + row0) * PDH + k0 + gc0 * 8);
        CP_ASYNC16(bT + d1, Bm + (long)(n0 + row1) * PDH + k0 + gc1 * 8);
        CP_COMMIT();
    };

    const int NSTAGE = PDH / 32;
    issue(0);
    issue(1);

    for (int s = 0; s < NSTAGE; s++) {
        if (s + 2 < NSTAGE) { issue(s + 2); asm volatile("cp.async.wait_group 2;"); }
        else if (s + 1 < NSTAGE) { asm volatile("cp.async.wait_group 1;"); }
        else { asm volatile("cp.async.wait_group 0;"); }
        __syncthreads();

        const int st = s & (NSTS - 1);
        const uint32_t aT = sbase + st * BSTG * 4;
        const uint32_t bT = sbase + (NSTS + st) * BSTG * 4;

#pragma unroll
        for (int kk = 0; kk < 16; kk += 8) {
            uint32_t af[4][4];
#pragma unroll
            for (int mt = 0; mt < 4; mt++)
                LDSM4(af[mt][0], af[mt][1], af[mt][2], af[mt][3], aT + aoff[mt] + kk * 4);
            uint32_t bfr[4][2];
#pragma unroll
            for (int p = 0; p < 2; p++)
                LDSM4(bfr[2*p][0], bfr[2*p][1], bfr[2*p+1][0], bfr[2*p+1][1],
                      bT + boff[p] + kk * 4);
#pragma unroll
            for (int mt = 0; mt < 4; mt++)
#pragma unroll
                for (int nt = 0; nt < 4; nt++)
                    MMA_BF16(acc[mt][nt], af[mt], bfr[nt]);
        }
    }
    __syncthreads();

#pragma unroll
    for (int mt = 0; mt < 4; mt++) {
        const int rL = m0 + warpM*64 + mt*16 + g;
        const int rH = rL + 8;
#pragma unroll
        for (int nt = 0; nt < 4; nt++) {
            const int c = n0 + warpN*32 + nt*8 + t*2;
            uint32_t* cz = (uint32_t*)Cg + ((long)z * PL * PL >> 1);
            cz[((long)rL*PL + c) >> 1] = f2bf2(acc[mt][nt][0], acc[mt][nt][1]);
            cz[((long)rH*PL + c) >> 1] = f2bf2(acc[mt][nt][2], acc[mt][nt][3]);
        }
    }

#pragma unroll
    for (int nt = 0; nt < 4; nt++) {
        float s0 = 0.f, s1 = 0.f;
#pragma unroll
        for (int mt = 0; mt < 4; mt++) {
            s0 += acc[mt][nt][0] + acc[mt][nt][2];
            s1 += acc[mt][nt][1] + acc[mt][nt][3];
        }
        const int cl = warpN*32 + nt*8 + t*2;
        atomicAdd(&colsum[cl],   s0);
        atomicAdd(&colsum[cl+1], s1);
    }
    __syncthreads();
    if (tid < 128) {
        const int h = z & 7;
        atomicAdd(&mhp[h*PL + n0 + tid], colsum[tid] * (1.0f / (float)(PB*PL)));
    }
}

// ================= fused attention (pipelined across phases) =================
#define FA_STR 132
#define F_PQ_OFF (128*FA_STR)
#define F_PK_OFF (2*128*FA_STR)
#define F_PK_STG 5120
#define F23_SMEM ((F_PK_OFF + 4*F_PK_STG)*4)  // 217088

__global__ __launch_bounds__(512, 1)
void fused_attn(const __nv_bfloat16* __restrict__ qprojg, const __nv_bfloat16* __restrict__ kvg,
                const __nv_bfloat16* __restrict__ pkg, const __nv_bfloat16* __restrict__ vtg,
                const float* __restrict__ mh, __nv_bfloat16* __restrict__ attn,
                const float* __restrict__ alpha_p, const float* __restrict__ beta_p)
{
    extern __shared__ __align__(16) uint32_t sm[];
    __shared__ float den_s[128];
    __shared__ float cs_s[256];
    const uint32_t sbase = smem_u32(sm);

    const int tid = threadIdx.x;
    const int lane = tid & 31;
    const int warpId = tid >> 5;
    const int g = lane >> 2;
    const int t = lane & 3;
    const int warpM = warpId >> 3;
    const int warpN = warpId & 7;
    const int m0 = blockIdx.x * 128;
    const int z  = blockIdx.y;
    const int h  = z & 7;
    const __nv_bfloat16* PK = pkg + (long)z * PL * PDH;
    const __nv_bfloat16* VT = vtg + (long)z * PDH * PL;

    const int br0 = tid >> 2,         bc0 = tid & 3;
    const int br1 = (tid + 512) >> 2, bc1 = (tid + 512) & 3;
    const uint32_t bd0 = (br0 * PSTR + bc0 * 4) * 4;
    const uint32_t bd1 = (br1 * PSTR + bc1 * 4) * 4;

    auto issue1 = [&](int s) {
        const int st = s & 3;
        const uint32_t kT = sbase + (F_PK_OFF + st * F_PK_STG) * 4;
        const int k0 = s * 32;
        CP_ASYNC16(kT + bd0, PK + (long)br0 * PDH + k0 + bc0 * 8);
        CP_ASYNC16(kT + bd1, PK + (long)br1 * PDH + k0 + bc1 * 8);
        CP_COMMIT();
    };
    auto issue2 = [&](int s) {
        const int st = s & 3;
        const uint32_t vT = sbase + (F_PK_OFF + st * F_PK_STG) * 4;
        const int k0 = s * 32;
        CP_ASYNC16(vT + bd0, VT + (long)br0 * PL + k0 + bc0 * 8);
        CP_ASYNC16(vT + bd1, VT + (long)br1 * PL + k0 + bc1 * 8);
        CP_COMMIT();
    };

    issue1(0); issue1(1);

    if (tid < 128) den_s[tid] = 0.f;

    const float a = *alpha_p, bt = *beta_p;

    if (tid < 256) {
        float c = 0.f;
        for (int hp = 0; hp < h; hp++) c = bt * c + a * mh[hp*PL + tid];
        cs_s[tid] = c;
    }
    __syncthreads();

    {
        const uint32_t* qU  = (const uint32_t*)qprojg + (((long)z * PL + m0) * PDH >> 1);
        const uint32_t* kvU = (const uint32_t*)kvg   + (((long)z * PL + m0) * PL  >> 1);
        for (int i = tid; i < 128*128; i += 512) {
            const int row = i >> 7, cp = i & 127;
            const float2 q2 = bf2f(qU[row * 128 + cp]);
            const float2 v2 = bf2f(kvU[row * 128 + cp]);
            const float c0 = cs_s[cp*2], c1 = cs_s[cp*2 + 1];
            const float qm0 = q2.x * (c0 + a * (v2.x - c0));
            const float qm1 = q2.y * (c1 + a * (v2.y - c1));
            sm[F_PQ_OFF + row * FA_STR + cp] = f2bf2(phif(qm0), phif(qm1));
        }
    }
    __syncthreads();

    uint32_t aoffF[4];
#pragma unroll
    for (int mt = 0; mt < 4; mt++) {
        const int ar = warpM * 64 + mt * 16 + (lane & 15);
        const int ac = (lane >> 4) * 4;
        aoffF[mt] = (ar * FA_STR + ac) * 4;
    }
    uint32_t boff[2];
#pragma unroll
    for (int p = 0; p < 2; p++) {
        const int brr = warpN * 32 + p * 16 + (lane & 7) + ((lane >> 4) << 3);
        const int bcc = ((lane >> 3) & 1) * 4;
        boff[p] = (brr * PSTR + bcc) * 4;
    }

    float acc[4][4][4];
#pragma unroll
    for (int mt = 0; mt < 4; mt++)
#pragma unroll
        for (int nt = 0; nt < 4; nt++)
#pragma unroll
            for (int i = 0; i < 4; i++) acc[mt][nt][i] = 0.f;

    const int NS1 = PDH / 32;
    for (int s = 0; s < NS1; s++) {
        if (s + 2 < NS1) { issue1(s + 2); asm volatile("cp.async.wait_group 2;"); }
        else if (s + 1 < NS1) { asm volatile("cp.async.wait_group 1;"); }
        else { asm volatile("cp.async.wait_group 0;"); }
        __syncthreads();
        const uint32_t qT = sbase + (F_PQ_OFF + s * 16) * 4;
        const uint32_t kT = sbase + (F_PK_OFF + (s & 3) * F_PK_STG) * 4;
#pragma unroll
        for (int kk = 0; kk < 16; kk += 8) {
            uint32_t af[4][4];
#pragma unroll
            for (int mt = 0; mt < 4; mt++)
                LDSM4(af[mt][0], af[mt][1], af[mt][2], af[mt][3], qT + aoffF[mt] + kk * 4);
            uint32_t bfr[4][2];
#pragma unroll
            for (int p = 0; p < 2; p++)
                LDSM4(bfr[2*p][0], bfr[2*p][1], bfr[2*p+1][0], bfr[2*p+1][1],
                      kT + boff[p] + kk * 4);
#pragma unroll
            for (int mt = 0; mt < 4; mt++)
#pragma unroll
                for (int nt = 0; nt < 4; nt++)
                    MMA_BF16(acc[mt][nt], af[mt], bfr[nt]);
        }
    }

    issue2(0); issue2(1);

#pragma unroll
    for (int mt = 0; mt < 4; mt++) {
        const int lrL = warpM*64 + mt*16 + g;
        const int lrH = lrL + 8;
        const int rL = m0 + lrL, rH = m0 + lrH;
        float sL = 0.f, sH = 0.f;
#pragma unroll
        for (int nt = 0; nt < 4; nt++) {
            const int c = warpN*32 + nt*8 + t*2;
            const float wLx = (c   <= rL) ? acc[mt][nt][0] : 0.f;
            const float wLy = (c+1 <= rL) ? acc[mt][nt][1] : 0.f;
            const float wHx = (c   <= rH) ? acc[mt][nt][2] : 0.f;
            const float wHy = (c+1 <= rH) ? acc[mt][nt][3] : 0.f;
            sL += wLx + wLy;
            sH += wHx + wHy;
            sm[lrL * FA_STR + (c >> 1)] = f2bf2(wLx, wLy);
            sm[lrH * FA_STR + (c >> 1)] = f2bf2(wHx, wHy);
        }
        sL += __shfl_xor_sync(0xffffffffu, sL, 1);
        sL += __shfl_xor_sync(0xffffffffu, sL, 2);
        sH += __shfl_xor_sync(0xffffffffu, sH, 1);
        sH += __shfl_xor_sync(0xffffffffu, sH, 2);
        if (t == 0) {
            atomicAdd(&den_s[lrL], sL);
            atomicAdd(&den_s[lrH], sH);
        }
    }
    __syncthreads();

#pragma unroll
    for (int mt = 0; mt < 4; mt++)
#pragma unroll
        for (int nt = 0; nt < 4; nt++)
#pragma unroll
            for (int i = 0; i < 4; i++) acc[mt][nt][i] = 0.f;

    const int NS2 = PL / 32;
    for (int s = 0; s < NS2; s++) {
        if (s + 2 < NS2) { issue2(s + 2); asm volatile("cp.async.wait_group 2;"); }
        else if (s + 1 < NS2) { asm volatile("cp.async.wait_group 1;"); }
        else { asm volatile("cp.async.wait_group 0;"); }
        __syncthreads();
        const uint32_t vT = sbase + (F_PK_OFF + (s & 3) * F_PK_STG) * 4;
        const uint32_t aBase = sbase + (s * 16) * 4;
#pragma unroll
        for (int kk = 0; kk < 16; kk += 8) {
            uint32_t af[4][4];
#pragma unroll
            for (int mt = 0; mt < 4; mt++)
                LDSM4(af[mt][0], af[mt][1], af[mt][2], af[mt][3], aBase + aoffF[mt] + kk * 4);
            uint32_t bfr[4][2];
#pragma unroll
            for (int p = 0; p < 2; p++)
                LDSM4(bfr[2*p][0], bfr[2*p][1], bfr[2*p+1][0], bfr[2*p+1][1],
                      vT + boff[p] + kk * 4);
#pragma unroll
            for (int mt = 0; mt < 4; mt++)
#pragma unroll
                for (int nt = 0; nt < 4; nt++)
                    MMA_BF16(acc[mt][nt], af[mt], bfr[nt]);
        }
    }

    const int b = z >> 3;
#pragma unroll
    for (int mt = 0; mt < 4; mt++) {
        const int lrL = warpM*64 + mt*16 + g;
        const int lrH = lrL + 8;
        const int rL = m0 + lrL, rH = m0 + lrH;
        const float invL = 1.0f / fmaxf(den_s[lrL], 1e-8f);
        const float invH = 1.0f / fmaxf(den_s[lrH], 1e-8f);
#pragma unroll
        for (int nt = 0; nt < 4; nt++) {
            const int c = warpN*32 + nt*8 + t*2;
            const long iL = ((long)(b*PL + rL))*PD + h*PDH + c;
            const long iH = ((long)(b*PL + rH))*PD + h*PDH + c;
            ((uint32_t*)attn)[iL >> 1] = f2bf2(acc[mt][nt][0]*invL, acc[mt][nt][1]*invL);
            ((uint32_t*)attn)[iH >> 1] = f2bf2(acc[mt][nt][2]*invH, acc[mt][nt][3]*invH);
        }
    }
}

__global__ void ln_kernel(const float* __restrict__ q, const float* __restrict__ o,
                          const float* __restrict__ g, const float* __restrict__ be,
                          float* __restrict__ out) {
    const int tk = blockIdx.x;
    const int tid = threadIdx.x;
    __shared__ float red[256];
    const float* xq = q + (long)tk * PD;
    const float* xo = o + (long)tk * PD;
    float x[8];
    float s = 0.f;
#pragma unroll
    for (int i = 0; i < 8; i++) {
        x[i] = xq[tid + i*256] + xo[tid + i*256];
        s += x[i];
    }
    red[tid] = s; __syncthreads();
    for (int st = 128; st > 0; st >>= 1) {
        if (tid < st) red[tid] += red[tid + st];
        __syncthreads();
    }
    const float mu = red[0] * (1.0f / PD);
    __syncthreads();
    float v = 0.f;
#pragma unroll
    for (int i = 0; i < 8; i++) { const float dd = x[i] - mu; v += dd*dd; }
    red[tid] = v; __syncthreads();
    for (int st = 128; st > 0; st >>= 1) {
        if (tid < st) red[tid] += red[tid + st];
        __syncthreads();
    }
    const float inv = rsqrtf(red[0] * (1.0f / PD) + 1e-5f);
#pragma unroll
    for (int i = 0; i < 8; i++) {
        const int c = tid + i*256;
        out[(long)tk*PD + c] = (x[i] - mu) * inv * g[c] + be[c];
    }
}

// ---------------- launch ----------------
extern "C" void kernel_launch(void* const* d_in, const int* in_sizes, int n_in,
                              void* d_out, int out_size) {
    const float* query = (const float*)d_in[0];
    const float* key   = (const float*)d_in[1];
    const float* value = (const float*)d_in[2];
    const float* Wq    = (const float*)d_in[3];
    const float* Wk    = (const float*)d_in[4];
    const float* Wv    = (const float*)d_in[5];
    const float* Wo    = (const float*)d_in[6];
    const float* bo    = (const float*)d_in[7];
    const float* ln_g  = (const float*)d_in[8];
    const float* ln_b  = (const float*)d_in[9];
    const float* alpha = (const float*)d_in[10];
    const float* beta  = (const float*)d_in[11];
    float* out = (float*)d_out;

    float *o, *mh;
    __nv_bfloat16 *qproj, *kvbf, *kbhl, *vbhl, *vt, *pk, *attnbf;
    __nv_bfloat16 *qbf, *kbf, *vbf, *wqbf, *wkbf, *wvbf, *wobf;
    cudaGetSymbolAddress((void**)&o,  g_o);
    cudaGetSymbolAddress((void**)&mh, g_mh);
    cudaGetSymbolAddress((void**)&qproj, g_qproj);
    cudaGetSymbolAddress((void**)&kvbf, g_kvbf);
    cudaGetSymbolAddress((void**)&kbhl, g_kbhl);
    cudaGetSymbolAddress((void**)&vbhl, g_vbhl);
    cudaGetSymbolAddress((void**)&vt, g_vt);
    cudaGetSymbolAddress((void**)&pk, g_pk);
    cudaGetSymbolAddress((void**)&attnbf, g_attnbf);
    cudaGetSymbolAddress((void**)&qbf, g_qbf);
    cudaGetSymbolAddress((void**)&kbf, g_kbf);
    cudaGetSymbolAddress((void**)&vbf, g_vbf);
    cudaGetSymbolAddress((void**)&wqbf, g_wqbf);
    cudaGetSymbolAddress((void**)&wkbf, g_wkbf);
    cudaGetSymbolAddress((void**)&wvbf, g_wvbf);
    cudaGetSymbolAddress((void**)&wobf, g_wobf);

    cudaFuncSetAttribute(big3_gemm, cudaFuncAttributeMaxDynamicSharedMemorySize, BIG_SMEM);
    cudaFuncSetAttribute(bigo_gemm, cudaFuncAttributeMaxDynamicSharedMemorySize, BIG_SMEM);
    cudaFuncSetAttribute(kv_vt_kernel, cudaFuncAttributeMaxDynamicSharedMemorySize, BAT_SMEM);
    cudaFuncSetAttribute(fused_attn, cudaFuncAttributeMaxDynamicSharedMemorySize, F23_SMEM);

    dim3 gBig3(PD/128, PT/256, 3);
    dim3 gBigO(PD/128, PT/256, 1);
    dim3 gKV(2, 2, 96);            // 256 kv CTAs + 128 vt CTAs, one launch
    dim3 gFA(2, BH);

    // 1. all conversions + mh zero
    CvtArgs ca;
    ca.src[0] = query; ca.dst[0] = qbf;
    ca.src[1] = key;   ca.dst[1] = kbf;
    ca.src[2] = value; ca.dst[2] = vbf;
    ca.src[3] = Wq;    ca.dst[3] = wqbf;
    ca.src[4] = Wk;    ca.dst[4] = wkbf;
    ca.src[5] = Wv;    ca.dst[5] = wvbf;
    ca.src[6] = Wo;    ca.dst[6] = wobf;
    ca.mh = mh;
    cvt_all_kernel<<<7169, 256>>>(ca);

    // 2. merged Q/K/V projections
    big3_gemm<<<gBig3, 512, BIG_SMEM>>>(qbf, kbf, vbf, wqbf, wkbf, wvbf,
                                        qproj, kbhl, pk, vbhl);

    // 3. kv GEMM (+ column-mean -> mh) AND V^T, one launch (independent work overlapped)
    kv_vt_kernel<<<gKV, 256, BAT_SMEM>>>(kbhl, vbhl, kvbf, mh, vt);

    // 4. fused attention (pipelined phases)
    fused_attn<<<gFA, 512, F23_SMEM>>>(qproj, kvbf, pk, vt, mh, attnbf, alpha, beta);

    // 5. o = attn @ Wo^T + bo
    bigo_gemm<<<gBigO, 512, BIG_SMEM>>>(attnbf, wobf, o, bo);

    // 6. residual + layernorm
    ln_kernel<<<PT, 256>>>(query, o, ln_g, ln_b, out);
}

// round 17
// speedup vs baseline: 1.0151x; 1.0151x over previous
#include <cuda_runtime.h>
#include <cuda_bf16.h>
#include <math.h>
#include <stdint.h>

// Problem constants
#define PB 8
#define PL 256
#define PD 2048
#define PH 8
#define PDH 256
#define PT (PB*PL)
#define BH (PB*PH)

// ---------------- scratch ----------------
__device__ float g_o[PT*PD];
__device__ float g_mh[PH*PL];

__device__ __nv_bfloat16 g_qproj[BH*PL*PDH];
__device__ __nv_bfloat16 g_kvbf[BH*PL*PL];
__device__ __nv_bfloat16 g_kbhl[BH*PL*PDH];
__device__ __nv_bfloat16 g_vbhl[BH*PL*PDH];
__device__ __nv_bfloat16 g_vt[BH*PDH*PL];
__device__ __nv_bfloat16 g_pk[BH*PL*PDH];
__device__ __nv_bfloat16 g_attnbf[PT*PD];

__device__ __nv_bfloat16 g_qbf[PT*PD];
__device__ __nv_bfloat16 g_kbf[PT*PD];
__device__ __nv_bfloat16 g_vbf[PT*PD];
__device__ __nv_bfloat16 g_wqbf[PD*PD];
__device__ __nv_bfloat16 g_wkbf[PD*PD];
__device__ __nv_bfloat16 g_wvbf[PD*PD];
__device__ __nv_bfloat16 g_wobf[PD*PD];

// ---------------- helpers ----------------
__device__ __forceinline__ uint32_t f2bf2(float lo, float hi) {
    __nv_bfloat162 h = __float22bfloat162_rn(make_float2(lo, hi));
    return *(uint32_t*)&h;
}
__device__ __forceinline__ float2 bf2f(uint32_t r) {
    return __bfloat1622float2(*(__nv_bfloat162*)&r);
}
__device__ __forceinline__ float phif(float x) {
    return x > 0.f ? x + 1.f : __expf(x);
}
__device__ __forceinline__ uint32_t smem_u32(const void* p) {
    uint32_t a;
    asm("{ .reg .u64 t; cvta.to.shared.u64 t, %1; cvt.u32.u64 %0, t; }" : "=r"(a) : "l"(p));
    return a;
}
#define CP_ASYNC16(dst, src) \
    asm volatile("cp.async.cg.shared.global [%0], [%1], 16;" :: "r"(dst), "l"(src))
#define CP_COMMIT() asm volatile("cp.async.commit_group;")
#define LDSM4(r0, r1, r2, r3, a) \
    asm volatile("ldmatrix.sync.aligned.m8n8.x4.shared.b16 {%0,%1,%2,%3}, [%4];" \
        : "=r"(r0), "=r"(r1), "=r"(r2), "=r"(r3) : "r"(a))
#define MMA_BF16(acc, af, bfr) \
    asm volatile( \
        "mma.sync.aligned.m16n8k16.row.col.f32.bf16.bf16.f32 " \
        "{%0,%1,%2,%3}, {%4,%5,%6,%7}, {%8,%9}, {%0,%1,%2,%3};\n" \
        : "+f"((acc)[0]), "+f"((acc)[1]), "+f"((acc)[2]), "+f"((acc)[3]) \
        : "r"((af)[0]), "r"((af)[1]), "r"((af)[2]), "r"((af)[3]), \
          "r"((bfr)[0]), "r"((bfr)[1]))

#define PSTR 20

// ================= merged fp32->bf16 conversions + mh zero =================
struct CvtArgs {
    const float* src[7];
    __nv_bfloat16* dst[7];
    float* mh;
};

__global__ void cvt_all_kernel(CvtArgs a) {
    if (blockIdx.x >= 7168) {
        for (int j = threadIdx.x; j < PH*PL; j += 256) a.mh[j] = 0.f;
        return;
    }
    const int job = blockIdx.x >> 10;
    const long blk = blockIdx.x & 1023;
    const float* __restrict__ src = a.src[job];
    __nv_bfloat16* __restrict__ dst = a.dst[job];
    const long i = (blk * 256 + threadIdx.x) * 16;
    const float4 v0 = *(const float4*)(src + i);
    const float4 v1 = *(const float4*)(src + i + 4);
    const float4 v2 = *(const float4*)(src + i + 8);
    const float4 v3 = *(const float4*)(src + i + 12);
    uint4 p0, p1;
    p0.x = f2bf2(v0.x, v0.y); p0.y = f2bf2(v0.z, v0.w);
    p0.z = f2bf2(v1.x, v1.y); p0.w = f2bf2(v1.z, v1.w);
    p1.x = f2bf2(v2.x, v2.y); p1.y = f2bf2(v2.z, v2.w);
    p1.z = f2bf2(v3.x, v3.y); p1.w = f2bf2(v3.z, v3.w);
    *(uint4*)(dst + i) = p0;
    *(uint4*)(dst + i + 8) = p1;
}

// ================= big bf16 GEMM core (256x128 tile, 512 threads) =================
#define STGA (256*PSTR)
#define STGB (128*PSTR)
#define NSTB 6
#define BIG_SMEM (NSTB*(STGA + STGB)*4)

__global__ __launch_bounds__(512, 1)
void big3_gemm(const __nv_bfloat16* __restrict__ qbf, const __nv_bfloat16* __restrict__ kbf,
               const __nv_bfloat16* __restrict__ vbf,
               const __nv_bfloat16* __restrict__ wq, const __nv_bfloat16* __restrict__ wk,
               const __nv_bfloat16* __restrict__ wv,
               __nv_bfloat16* __restrict__ Qo, __nv_bfloat16* __restrict__ kbhl,
               __nv_bfloat16* __restrict__ pk, __nv_bfloat16* __restrict__ vbhl)
{
    extern __shared__ __align__(16) uint32_t sm[];
    const uint32_t sbase = smem_u32(sm);

    const int z = blockIdx.z;
    const __nv_bfloat16* __restrict__ Ag = (z == 0) ? qbf : (z == 1) ? kbf : vbf;
    const __nv_bfloat16* __restrict__ Wg = (z == 0) ? wq  : (z == 1) ? wk  : wv;

    const int tid = threadIdx.x;
    const int lane = tid & 31;
    const int warpId = tid >> 5;
    const int g = lane >> 2;
    const int t = lane & 3;
    const int warpM = warpId >> 2;
    const int warpN = warpId & 3;
    const int m0 = blockIdx.y * 256;
    const int n0 = blockIdx.x * 128;

    const int ga0 = tid, ga1 = tid + 512;
    const int ar0 = ga0 >> 2, ac0 = ga0 & 3;
    const int ar1 = ga1 >> 2, ac1 = ga1 & 3;
    const int br  = tid >> 2, bc = tid & 3;
    const uint32_t da0 = (ar0 * PSTR + ac0 * 4) * 4;
    const uint32_t da1 = (ar1 * PSTR + ac1 * 4) * 4;
    const uint32_t db  = (br  * PSTR + bc  * 4) * 4;

    uint32_t aoff[4];
#pragma unroll
    for (int mt = 0; mt < 4; mt++) {
        const int ar = warpM * 64 + mt * 16 + (lane & 15);
        const int ac = (lane >> 4) * 4;
        aoff[mt] = (ar * PSTR + ac) * 4;
    }
    uint32_t boff[2];
#pragma unroll
    for (int p = 0; p < 2; p++) {
        const int brr = warpN * 32 + p * 16 + (lane & 7) + ((lane >> 4) << 3);
        const int bcc = ((lane >> 3) & 1) * 4;
        boff[p] = (brr * PSTR + bcc) * 4;
    }

    float acc[4][4][4];
#pragma unroll
    for (int mt = 0; mt < 4; mt++)
#pragma unroll
        for (int nt = 0; nt < 4; nt++)
#pragma unroll
            for (int i = 0; i < 4; i++) acc[mt][nt][i] = 0.f;

    auto issue = [&](int s) {
        const int st = s % NSTB;
        const uint32_t aT = sbase + st * STGA * 4;
        const uint32_t bT = sbase + (NSTB * STGA + st * STGB) * 4;
        const int k0 = s * 32;
        CP_ASYNC16(aT + da0, Ag + (long)(m0 + ar0) * PD + k0 + ac0 * 8);
        CP_ASYNC16(aT + da1, Ag + (long)(m0 + ar1) * PD + k0 + ac1 * 8);
        CP_ASYNC16(bT + db,  Wg + (long)(n0 + br)  * PD + k0 + bc  * 8);
        CP_COMMIT();
    };

    const int NSTAGE = PD / 32;
    issue(0); issue(1); issue(2);

    for (int s = 0; s < NSTAGE; s++) {
        if (s + 3 < NSTAGE) { issue(s + 3); asm volatile("cp.async.wait_group 3;"); }
        else if (s + 2 < NSTAGE) { asm volatile("cp.async.wait_group 2;"); }
        else if (s + 1 < NSTAGE) { asm volatile("cp.async.wait_group 1;"); }
        else { asm volatile("cp.async.wait_group 0;"); }
        __syncthreads();

        const int st = s % NSTB;
        const uint32_t aT = sbase + st * STGA * 4;
        const uint32_t bT = sbase + (NSTB * STGA + st * STGB) * 4;

#pragma unroll
        for (int kk = 0; kk < 16; kk += 8) {
            uint32_t af[4][4];
#pragma unroll
            for (int mt = 0; mt < 4; mt++)
                LDSM4(af[mt][0], af[mt][1], af[mt][2], af[mt][3], aT + aoff[mt] + kk * 4);
            uint32_t bfr[4][2];
#pragma unroll
            for (int p = 0; p < 2; p++)
                LDSM4(bfr[2*p][0], bfr[2*p][1], bfr[2*p+1][0], bfr[2*p+1][1],
                      bT + boff[p] + kk * 4);
#pragma unroll
            for (int mt = 0; mt < 4; mt++)
#pragma unroll
                for (int nt = 0; nt < 4; nt++)
                    MMA_BF16(acc[mt][nt], af[mt], bfr[nt]);
        }
    }

#pragma unroll
    for (int mt = 0; mt < 4; mt++) {
        const int rL = m0 + warpM*64 + mt*16 + g;
        const int rH = rL + 8;
#pragma unroll
        for (int nt = 0; nt < 4; nt++) {
            const int c = n0 + warpN*32 + nt*8 + t*2;
            float2 vL = make_float2(acc[mt][nt][0], acc[mt][nt][1]);
            float2 vH = make_float2(acc[mt][nt][2], acc[mt][nt][3]);
            const int h = c >> 8, d = c & 255;
            const int bL = rL >> 8, lL = rL & 255;
            const int bR = rH >> 8, lH = rH & 255;
            const long iL = (((long)(bL*PH + h))*PL + lL)*PDH + d;
            const long iH = (((long)(bR*PH + h))*PL + lH)*PDH + d;
            if (z == 0) {
                ((uint32_t*)Qo)[iL >> 1] = f2bf2(vL.x, vL.y);
                ((uint32_t*)Qo)[iH >> 1] = f2bf2(vH.x, vH.y);
            } else if (z == 1) {
                ((uint32_t*)kbhl)[iL >> 1] = f2bf2(vL.x, vL.y);
                ((uint32_t*)kbhl)[iH >> 1] = f2bf2(vH.x, vH.y);
                ((uint32_t*)pk)[iL >> 1] = f2bf2(phif(vL.x), phif(vL.y));
                ((uint32_t*)pk)[iH >> 1] = f2bf2(phif(vH.x), phif(vH.y));
            } else {
                ((uint32_t*)vbhl)[iL >> 1] = f2bf2(vL.x, vL.y);
                ((uint32_t*)vbhl)[iH >> 1] = f2bf2(vH.x, vH.y);
            }
        }
    }
}

__global__ __launch_bounds__(512, 1)
void bigo_gemm(const __nv_bfloat16* __restrict__ Ag, const __nv_bfloat16* __restrict__ Wg,
               float* __restrict__ Cg, const float* __restrict__ bias)
{
    extern __shared__ __align__(16) uint32_t sm[];
    const uint32_t sbase = smem_u32(sm);

    const int tid = threadIdx.x;
    const int lane = tid & 31;
    const int warpId = tid >> 5;
    const int g = lane >> 2;
    const int t = lane & 3;
    const int warpM = warpId >> 2;
    const int warpN = warpId & 3;
    const int m0 = blockIdx.y * 256;
    const int n0 = blockIdx.x * 128;

    const int ga0 = tid, ga1 = tid + 512;
    const int ar0 = ga0 >> 2, ac0 = ga0 & 3;
    const int ar1 = ga1 >> 2, ac1 = ga1 & 3;
    const int br  = tid >> 2, bc = tid & 3;
    const uint32_t da0 = (ar0 * PSTR + ac0 * 4) * 4;
    const uint32_t da1 = (ar1 * PSTR + ac1 * 4) * 4;
    const uint32_t db  = (br  * PSTR + bc  * 4) * 4;

    uint32_t aoff[4];
#pragma unroll
    for (int mt = 0; mt < 4; mt++) {
        const int ar = warpM * 64 + mt * 16 + (lane & 15);
        const int ac = (lane >> 4) * 4;
        aoff[mt] = (ar * PSTR + ac) * 4;
    }
    uint32_t boff[2];
#pragma unroll
    for (int p = 0; p < 2; p++) {
        const int brr = warpN * 32 + p * 16 + (lane & 7) + ((lane >> 4) << 3);
        const int bcc = ((lane >> 3) & 1) * 4;
        boff[p] = (brr * PSTR + bcc) * 4;
    }

    float acc[4][4][4];
#pragma unroll
    for (int mt = 0; mt < 4; mt++)
#pragma unroll
        for (int nt = 0; nt < 4; nt++)
#pragma unroll
            for (int i = 0; i < 4; i++) acc[mt][nt][i] = 0.f;

    auto issue = [&](int s) {
        const int st = s % NSTB;
        const uint32_t aT = sbase + st * STGA * 4;
        const uint32_t bT = sbase + (NSTB * STGA + st * STGB) * 4;
        const int k0 = s * 32;
        CP_ASYNC16(aT + da0, Ag + (long)(m0 + ar0) * PD + k0 + ac0 * 8);
        CP_ASYNC16(aT + da1, Ag + (long)(m0 + ar1) * PD + k0 + ac1 * 8);
        CP_ASYNC16(bT + db,  Wg + (long)(n0 + br)  * PD + k0 + bc  * 8);
        CP_COMMIT();
    };

    const int NSTAGE = PD / 32;
    issue(0); issue(1); issue(2);

    for (int s = 0; s < NSTAGE; s++) {
        if (s + 3 < NSTAGE) { issue(s + 3); asm volatile("cp.async.wait_group 3;"); }
        else if (s + 2 < NSTAGE) { asm volatile("cp.async.wait_group 2;"); }
        else if (s + 1 < NSTAGE) { asm volatile("cp.async.wait_group 1;"); }
        else { asm volatile("cp.async.wait_group 0;"); }
        __syncthreads();

        const int st = s % NSTB;
        const uint32_t aT = sbase + st * STGA * 4;
        const uint32_t bT = sbase + (NSTB * STGA + st * STGB) * 4;

#pragma unroll
        for (int kk = 0; kk < 16; kk += 8) {
            uint32_t af[4][4];
#pragma unroll
            for (int mt = 0; mt < 4; mt++)
                LDSM4(af[mt][0], af[mt][1], af[mt][2], af[mt][3], aT + aoff[mt] + kk * 4);
            uint32_t bfr[4][2];
#pragma unroll
            for (int p = 0; p < 2; p++)
                LDSM4(bfr[2*p][0], bfr[2*p][1], bfr[2*p+1][0], bfr[2*p+1][1],
                      bT + boff[p] + kk * 4);
#pragma unroll
            for (int mt = 0; mt < 4; mt++)
#pragma unroll
                for (int nt = 0; nt < 4; nt++)
                    MMA_BF16(acc[mt][nt], af[mt], bfr[nt]);
        }
    }

#pragma unroll
    for (int mt = 0; mt < 4; mt++) {
        const int rL = m0 + warpM*64 + mt*16 + g;
        const int rH = rL + 8;
#pragma unroll
        for (int nt = 0; nt < 4; nt++) {
            const int c = n0 + warpN*32 + nt*8 + t*2;
            float2 bv = *(const float2*)&bias[c];
            *(float2*)&Cg[(long)rL*PD + c] = make_float2(acc[mt][nt][0] + bv.x, acc[mt][nt][1] + bv.y);
            *(float2*)&Cg[(long)rH*PD + c] = make_float2(acc[mt][nt][2] + bv.x, acc[mt][nt][3] + bv.y);
        }
    }
}

// ================= kv GEMM (128x128 tile, 256 threads) =================
#define BSTG (128*PSTR)
#define NSTS 4
#define BAT_SMEM (2*NSTS*BSTG*4)

__global__ __launch_bounds__(256, 2)
void kv_gemm(const __nv_bfloat16* __restrict__ Ag, const __nv_bfloat16* __restrict__ Bg,
             __nv_bfloat16* __restrict__ Cg, float* __restrict__ mhp)
{
    extern __shared__ __align__(16) uint32_t sm[];
    const uint32_t sbase = smem_u32(sm);
    __shared__ float colsum[128];

    const int tid = threadIdx.x;
    const int lane = tid & 31;
    const int warpId = tid >> 5;
    const int g = lane >> 2;
    const int t = lane & 3;
    const int warpM = warpId >> 2;
    const int warpN = warpId & 3;
    const int m0 = blockIdx.y * 128;
    const int n0 = blockIdx.x * 128;
    const int z  = blockIdx.z;
    const __nv_bfloat16* A  = Ag + (long)z * PL * PDH;
    const __nv_bfloat16* Bm = Bg + (long)z * PL * PDH;

    if (tid < 128) colsum[tid] = 0.f;

    const int gid0 = tid, gid1 = tid + 256;
    const int row0 = gid0 >> 2, gc0 = gid0 & 3;
    const int row1 = gid1 >> 2, gc1 = gid1 & 3;
    const uint32_t d0 = (row0 * PSTR + gc0 * 4) * 4;
    const uint32_t d1 = (row1 * PSTR + gc1 * 4) * 4;

    uint32_t aoff[4];
#pragma unroll
    for (int mt = 0; mt < 4; mt++) {
        const int ar = warpM * 64 + mt * 16 + (lane & 15);
        const int ac = (lane >> 4) * 4;
        aoff[mt] = (ar * PSTR + ac) * 4;
    }
    uint32_t boff[2];
#pragma unroll
    for (int p = 0; p < 2; p++) {
        const int br = warpN * 32 + p * 16 + (lane & 7) + ((lane >> 4) << 3);
        const int bc = ((lane >> 3) & 1) * 4;
        boff[p] = (br * PSTR + bc) * 4;
    }

    float acc[4][4][4];
#pragma unroll
    for (int mt = 0; mt < 4; mt++)
#pragma unroll
        for (int nt = 0; nt < 4; nt++)
#pragma unroll
            for (int i = 0; i < 4; i++) acc[mt][nt][i] = 0.f;

    auto issue = [&](int s) {
        const int st = s & (NSTS - 1);
        const uint32_t aT = sbase + st * BSTG * 4;
        const uint32_t bT = sbase + (NSTS + st) * BSTG * 4;
        const int k0 = s * 32;
        CP_ASYNC16(aT + d0, A  + (long)(m0 + row0) * PDH + k0 + gc0 * 8);
        CP_ASYNC16(aT + d1, A  + (long)(m0 + row1) * PDH + k0 + gc1 * 8);
        CP_ASYNC16(bT + d0, Bm + (long)(n0 + row0) * PDH + k0 + gc0 * 8);
        CP_ASYNC16(bT + d1, Bm + (long)(n0 + row1) * PDH + k0 + gc1 * 8);
        CP_COMMIT();
    };

    const int NSTAGE = PDH / 32;
    issue(0);
    issue(1);

    for (int s = 0; s < NSTAGE; s++) {
        if (s + 2 < NSTAGE) { issue(s + 2); asm volatile("cp.async.wait_group 2;"); }
        else if (s + 1 < NSTAGE) { asm volatile("cp.async.wait_group 1;"); }
        else { asm volatile("cp.async.wait_group 0;"); }
        __syncthreads();

        const int st = s & (NSTS - 1);
        const uint32_t aT = sbase + st * BSTG * 4;
        const uint32_t bT = sbase + (NSTS + st) * BSTG * 4;

#pragma unroll
        for (int kk = 0; kk < 16; kk += 8) {
            uint32_t af[4][4];
#pragma unroll
            for (int mt = 0; mt < 4; mt++)
                LDSM4(af[mt][0], af[mt][1], af[mt][2], af[mt][3], aT + aoff[mt] + kk * 4);
            uint32_t bfr[4][2];
#pragma unroll
            for (int p = 0; p < 2; p++)
                LDSM4(bfr[2*p][0], bfr[2*p][1], bfr[2*p+1][0], bfr[2*p+1][1],
                      bT + boff[p] + kk * 4);
#pragma unroll
            for (int mt = 0; mt < 4; mt++)
#pragma unroll
                for (int nt = 0; nt < 4; nt++)
                    MMA_BF16(acc[mt][nt], af[mt], bfr[nt]);
        }
    }
    __syncthreads();

#pragma unroll
    for (int mt = 0; mt < 4; mt++) {
        const int rL = m0 + warpM*64 + mt*16 + g;
        const int rH = rL + 8;
#pragma unroll
        for (int nt = 0; nt < 4; nt++) {
            const int c = n0 + warpN*32 + nt*8 + t*2;
            uint32_t* cz = (uint32_t*)Cg + ((long)z * PL * PL >> 1);
            cz[((long)rL*PL + c) >> 1] = f2bf2(acc[mt][nt][0], acc[mt][nt][1]);
            cz[((long)rH*PL + c) >> 1] = f2bf2(acc[mt][nt][2], acc[mt][nt][3]);
        }
    }

#pragma unroll
    for (int nt = 0; nt < 4; nt++) {
        float s0 = 0.f, s1 = 0.f;
#pragma unroll
        for (int mt = 0; mt < 4; mt++) {
            s0 += acc[mt][nt][0] + acc[mt][nt][2];
            s1 += acc[mt][nt][1] + acc[mt][nt][3];
        }
        const int cl = warpN*32 + nt*8 + t*2;
        atomicAdd(&colsum[cl],   s0);
        atomicAdd(&colsum[cl+1], s1);
    }
    __syncthreads();
    if (tid < 128) {
        const int h = z & 7;
        atomicAdd(&mhp[h*PL + n0 + tid], colsum[tid] * (1.0f / (float)(PB*PL)));
    }
}

// ================= V transpose =================
__global__ void vt_kernel(const __nv_bfloat16* __restrict__ in, __nv_bfloat16* __restrict__ out) {
    __shared__ __nv_bfloat16 tile[32][33];
    const int z = blockIdx.z;
    const int l0 = blockIdx.x * 32;
    const int d0 = blockIdx.y * 32;
    const int tx = threadIdx.x, ty = threadIdx.y;
    const __nv_bfloat16* src = in + (long)z * PL * PDH;
    __nv_bfloat16* dst = out + (long)z * PDH * PL;
#pragma unroll
    for (int j = 0; j < 4; j++)
        tile[ty*4 + j][tx] = src[(long)(l0 + ty*4 + j) * PDH + d0 + tx];
    __syncthreads();
#pragma unroll
    for (int j = 0; j < 4; j++)
        dst[(long)(d0 + ty*4 + j) * PL + l0 + tx] = tile[tx][ty*4 + j];
}

// ================= fused attention (pipelined across phases) =================
#define FA_STR 132
#define F_PQ_OFF (128*FA_STR)
#define F_PK_OFF (2*128*FA_STR)
#define F_PK_STG 5120
#define F23_SMEM ((F_PK_OFF + 4*F_PK_STG)*4)  // 217088

__global__ __launch_bounds__(512, 1)
void fused_attn(const __nv_bfloat16* __restrict__ qprojg, const __nv_bfloat16* __restrict__ kvg,
                const __nv_bfloat16* __restrict__ pkg, const __nv_bfloat16* __restrict__ vtg,
                const float* __restrict__ mh, __nv_bfloat16* __restrict__ attn,
                const float* __restrict__ alpha_p, const float* __restrict__ beta_p)
{
    extern __shared__ __align__(16) uint32_t sm[];
    __shared__ float den_s[128];
    __shared__ float cs_s[256];
    const uint32_t sbase = smem_u32(sm);

    const int tid = threadIdx.x;
    const int lane = tid & 31;
    const int warpId = tid >> 5;
    const int g = lane >> 2;
    const int t = lane & 3;
    const int warpM = warpId >> 3;
    const int warpN = warpId & 7;
    const int m0 = blockIdx.x * 128;
    const int z  = blockIdx.y;
    const int h  = z & 7;
    const __nv_bfloat16* PK = pkg + (long)z * PL * PDH;
    const __nv_bfloat16* VT = vtg + (long)z * PDH * PL;

    const int br0 = tid >> 2,         bc0 = tid & 3;
    const int br1 = (tid + 512) >> 2, bc1 = (tid + 512) & 3;
    const uint32_t bd0 = (br0 * PSTR + bc0 * 4) * 4;
    const uint32_t bd1 = (br1 * PSTR + bc1 * 4) * 4;

    auto issue1 = [&](int s) {
        const int st = s & 3;
        const uint32_t kT = sbase + (F_PK_OFF + st * F_PK_STG) * 4;
        const int k0 = s * 32;
        CP_ASYNC16(kT + bd0, PK + (long)br0 * PDH + k0 + bc0 * 8);
        CP_ASYNC16(kT + bd1, PK + (long)br1 * PDH + k0 + bc1 * 8);
        CP_COMMIT();
    };
    auto issue2 = [&](int s) {
        const int st = s & 3;
        const uint32_t vT = sbase + (F_PK_OFF + st * F_PK_STG) * 4;
        const int k0 = s * 32;
        CP_ASYNC16(vT + bd0, VT + (long)br0 * PL + k0 + bc0 * 8);
        CP_ASYNC16(vT + bd1, VT + (long)br1 * PL + k0 + bc1 * 8);
        CP_COMMIT();
    };

    issue1(0); issue1(1);

    if (tid < 128) den_s[tid] = 0.f;

    const float a = *alpha_p, bt = *beta_p;

    if (tid < 256) {
        float c = 0.f;
        for (int hp = 0; hp < h; hp++) c = bt * c + a * mh[hp*PL + tid];
        cs_s[tid] = c;
    }
    __syncthreads();

    {
        const uint32_t* qU  = (const uint32_t*)qprojg + (((long)z * PL + m0) * PDH >> 1);
        const uint32_t* kvU = (const uint32_t*)kvg   + (((long)z * PL + m0) * PL  >> 1);
        for (int i = tid; i < 128*128; i += 512) {
            const int row = i >> 7, cp = i & 127;
            const float2 q2 = bf2f(qU[row * 128 + cp]);
            const float2 v2 = bf2f(kvU[row * 128 + cp]);
            const float c0 = cs_s[cp*2], c1 = cs_s[cp*2 + 1];
            const float qm0 = q2.x * (c0 + a * (v2.x - c0));
            const float qm1 = q2.y * (c1 + a * (v2.y - c1));
            sm[F_PQ_OFF + row * FA_STR + cp] = f2bf2(phif(qm0), phif(qm1));
        }
    }
    __syncthreads();

    uint32_t aoffF[4];
#pragma unroll
    for (int mt = 0; mt < 4; mt++) {
        const int ar = warpM * 64 + mt * 16 + (lane & 15);
        const int ac = (lane >> 4) * 4;
        aoffF[mt] = (ar * FA_STR + ac) * 4;
    }
    uint32_t boff[2];
#pragma unroll
    for (int p = 0; p < 2; p++) {
        const int brr = warpN * 32 + p * 16 + (lane & 7) + ((lane >> 4) << 3);
        const int bcc = ((lane >> 3) & 1) * 4;
        boff[p] = (brr * PSTR + bcc) * 4;
    }

    float acc[4][4][4];
#pragma unroll
    for (int mt = 0; mt < 4; mt++)
#pragma unroll
        for (int nt = 0; nt < 4; nt++)
#pragma unroll
            for (int i = 0; i < 4; i++) acc[mt][nt][i] = 0.f;

    const int NS1 = PDH / 32;
    for (int s = 0; s < NS1; s++) {
        if (s + 2 < NS1) { issue1(s + 2); asm volatile("cp.async.wait_group 2;"); }
        else if (s + 1 < NS1) { asm volatile("cp.async.wait_group 1;"); }
        else { asm volatile("cp.async.wait_group 0;"); }
        __syncthreads();
        const uint32_t qT = sbase + (F_PQ_OFF + s * 16) * 4;
        const uint32_t kT = sbase + (F_PK_OFF + (s & 3) * F_PK_STG) * 4;
#pragma unroll
        for (int kk = 0; kk < 16; kk += 8) {
            uint32_t af[4][4];
#pragma unroll
            for (int mt = 0; mt < 4; mt++)
                LDSM4(af[mt][0], af[mt][1], af[mt][2], af[mt][3], qT + aoffF[mt] + kk * 4);
            uint32_t bfr[4][2];
#pragma unroll
            for (int p = 0; p < 2; p++)
                LDSM4(bfr[2*p][0], bfr[2*p][1], bfr[2*p+1][0], bfr[2*p+1][1],
                      kT + boff[p] + kk * 4);
#pragma unroll
            for (int mt = 0; mt < 4; mt++)
#pragma unroll
                for (int nt = 0; nt < 4; nt++)
                    MMA_BF16(acc[mt][nt], af[mt], bfr[nt]);
        }
    }

    issue2(0); issue2(1);

#pragma unroll
    for (int mt = 0; mt < 4; mt++) {
        const int lrL = warpM*64 + mt*16 + g;
        const int lrH = lrL + 8;
        const int rL = m0 + lrL, rH = m0 + lrH;
        float sL = 0.f, sH = 0.f;
#pragma unroll
        for (int nt = 0; nt < 4; nt++) {
            const int c = warpN*32 + nt*8 + t*2;
            const float wLx = (c   <= rL) ? acc[mt][nt][0] : 0.f;
            const float wLy = (c+1 <= rL) ? acc[mt][nt][1] : 0.f;
            const float wHx = (c   <= rH) ? acc[mt][nt][2] : 0.f;
            const float wHy = (c+1 <= rH) ? acc[mt][nt][3] : 0.f;
            sL += wLx + wLy;
            sH += wHx + wHy;
            sm[lrL * FA_STR + (c >> 1)] = f2bf2(wLx, wLy);
            sm[lrH * FA_STR + (c >> 1)] = f2bf2(wHx, wHy);
        }
        sL += __shfl_xor_sync(0xffffffffu, sL, 1);
        sL += __shfl_xor_sync(0xffffffffu, sL, 2);
        sH += __shfl_xor_sync(0xffffffffu, sH, 1);
        sH += __shfl_xor_sync(0xffffffffu, sH, 2);
        if (t == 0) {
            atomicAdd(&den_s[lrL], sL);
            atomicAdd(&den_s[lrH], sH);
        }
    }
    __syncthreads();

#pragma unroll
    for (int mt = 0; mt < 4; mt++)
#pragma unroll
        for (int nt = 0; nt < 4; nt++)
#pragma unroll
            for (int i = 0; i < 4; i++) acc[mt][nt][i] = 0.f;

    const int NS2 = PL / 32;
    for (int s = 0; s < NS2; s++) {
        if (s + 2 < NS2) { issue2(s + 2); asm volatile("cp.async.wait_group 2;"); }
        else if (s + 1 < NS2) { asm volatile("cp.async.wait_group 1;"); }
        else { asm volatile("cp.async.wait_group 0;"); }
        __syncthreads();
        const uint32_t vT = sbase + (F_PK_OFF + (s & 3) * F_PK_STG) * 4;
        const uint32_t aBase = sbase + (s * 16) * 4;
#pragma unroll
        for (int kk = 0; kk < 16; kk += 8) {
            uint32_t af[4][4];
#pragma unroll
            for (int mt = 0; mt < 4; mt++)
                LDSM4(af[mt][0], af[mt][1], af[mt][2], af[mt][3], aBase + aoffF[mt] + kk * 4);
            uint32_t bfr[4][2];
#pragma unroll
            for (int p = 0; p < 2; p++)
                LDSM4(bfr[2*p][0], bfr[2*p][1], bfr[2*p+1][0], bfr[2*p+1][1],
                      vT + boff[p] + kk * 4);
#pragma unroll
            for (int mt = 0; mt < 4; mt++)
#pragma unroll
                for (int nt = 0; nt < 4; nt++)
                    MMA_BF16(acc[mt][nt], af[mt], bfr[nt]);
        }
    }

    const int b = z >> 3;
#pragma unroll
    for (int mt = 0; mt < 4; mt++) {
        const int lrL = warpM*64 + mt*16 + g;
        const int lrH = lrL + 8;
        const int rL = m0 + lrL, rH = m0 + lrH;
        const float invL = 1.0f / fmaxf(den_s[lrL], 1e-8f);
        const float invH = 1.0f / fmaxf(den_s[lrH], 1e-8f);
#pragma unroll
        for (int nt = 0; nt < 4; nt++) {
            const int c = warpN*32 + nt*8 + t*2;
            const long iL = ((long)(b*PL + rL))*PD + h*PDH + c;
            const long iH = ((long)(b*PL + rH))*PD + h*PDH + c;
            ((uint32_t*)attn)[iL >> 1] = f2bf2(acc[mt][nt][0]*invL, acc[mt][nt][1]*invL);
            ((uint32_t*)attn)[iH >> 1] = f2bf2(acc[mt][nt][2]*invH, acc[mt][nt][3]*invH);
        }
    }
}

// ================= residual + layernorm (shuffle-based reduction) =================
__global__ void ln_kernel(const float* __restrict__ q, const float* __restrict__ o,
                          const float* __restrict__ g, const float* __restrict__ be,
                          float* __restrict__ out) {
    const int tk = blockIdx.x;
    const int tid = threadIdx.x;
    const int lane = tid & 31;
    const int wid = tid >> 5;
    __shared__ float red[8];
    const float* xq = q + (long)tk * PD;
    const float* xo = o + (long)tk * PD;
    float x[8];
    float s = 0.f;
#pragma unroll
    for (int i = 0; i < 8; i++) {
        x[i] = xq[tid + i*256] + xo[tid + i*256];
        s += x[i];
    }
#pragma unroll
    for (int d = 16; d > 0; d >>= 1) s += __shfl_xor_sync(0xffffffffu, s, d);
    if (lane == 0) red[wid] = s;
    __syncthreads();
    float tot = red[lane & 7];
#pragma unroll
    for (int d = 4; d > 0; d >>= 1) tot += __shfl_xor_sync(0xffffffffu, tot, d);
    // note: 8 values reduced over lanes 0..7 pattern; use butterfly over 8
    const float mu = tot * (1.0f / PD);

    float v = 0.f;
#pragma unroll
    for (int i = 0; i < 8; i++) { const float dd = x[i] - mu; v += dd*dd; }
#pragma unroll
    for (int d = 16; d > 0; d >>= 1) v += __shfl_xor_sync(0xffffffffu, v, d);
    __syncthreads();
    if (lane == 0) red[wid] = v;
    __syncthreads();
    float vt = red[lane & 7];
#pragma unroll
    for (int d = 4; d > 0; d >>= 1) vt += __shfl_xor_sync(0xffffffffu, vt, d);
    const float inv = rsqrtf(vt * (1.0f / PD) + 1e-5f);
#pragma unroll
    for (int i = 0; i < 8; i++) {
        const int c = tid + i*256;
        out[(long)tk*PD + c] = (x[i] - mu) * inv * g[c] + be[c];
    }
}

// ---------------- launch ----------------
extern "C" void kernel_launch(void* const* d_in, const int* in_sizes, int n_in,
                              void* d_out, int out_size) {
    const float* query = (const float*)d_in[0];
    const float* key   = (const float*)d_in[1];
    const float* value = (const float*)d_in[2];
    const float* Wq    = (const float*)d_in[3];
    const float* Wk    = (const float*)d_in[4];
    const float* Wv    = (const float*)d_in[5];
    const float* Wo    = (const float*)d_in[6];
    const float* bo    = (const float*)d_in[7];
    const float* ln_g  = (const float*)d_in[8];
    const float* ln_b  = (const float*)d_in[9];
    const float* alpha = (const float*)d_in[10];
    const float* beta  = (const float*)d_in[11];
    float* out = (float*)d_out;

    float *o, *mh;
    __nv_bfloat16 *qproj, *kvbf, *kbhl, *vbhl, *vt, *pk, *attnbf;
    __nv_bfloat16 *qbf, *kbf, *vbf, *wqbf, *wkbf, *wvbf, *wobf;
    cudaGetSymbolAddress((void**)&o,  g_o);
    cudaGetSymbolAddress((void**)&mh, g_mh);
    cudaGetSymbolAddress((void**)&qproj, g_qproj);
    cudaGetSymbolAddress((void**)&kvbf, g_kvbf);
    cudaGetSymbolAddress((void**)&kbhl, g_kbhl);
    cudaGetSymbolAddress((void**)&vbhl, g_vbhl);
    cudaGetSymbolAddress((void**)&vt, g_vt);
    cudaGetSymbolAddress((void**)&pk, g_pk);
    cudaGetSymbolAddress((void**)&attnbf, g_attnbf);
    cudaGetSymbolAddress((void**)&qbf, g_qbf);
    cudaGetSymbolAddress((void**)&kbf, g_kbf);
    cudaGetSymbolAddress((void**)&vbf, g_vbf);
    cudaGetSymbolAddress((void**)&wqbf, g_wqbf);
    cudaGetSymbolAddress((void**)&wkbf, g_wkbf);
    cudaGetSymbolAddress((void**)&wvbf, g_wvbf);
    cudaGetSymbolAddress((void**)&wobf, g_wobf);

    cudaFuncSetAttribute(big3_gemm, cudaFuncAttributeMaxDynamicSharedMemorySize, BIG_SMEM);
    cudaFuncSetAttribute(bigo_gemm, cudaFuncAttributeMaxDynamicSharedMemorySize, BIG_SMEM);
    cudaFuncSetAttribute(kv_gemm,  cudaFuncAttributeMaxDynamicSharedMemorySize, BAT_SMEM);
    cudaFuncSetAttribute(fused_attn, cudaFuncAttributeMaxDynamicSharedMemorySize, F23_SMEM);

    dim3 gBig3(PD/128, PT/256, 3);
    dim3 gBigO(PD/128, PT/256, 1);
    dim3 gKV(2, 2, BH);
    dim3 gFA(2, BH);

    // 1. all conversions + mh zero
    CvtArgs ca;
    ca.src[0] = query; ca.dst[0] = qbf;
    ca.src[1] = key;   ca.dst[1] = kbf;
    ca.src[2] = value; ca.dst[2] = vbf;
    ca.src[3] = Wq;    ca.dst[3] = wqbf;
    ca.src[4] = Wk;    ca.dst[4] = wkbf;
    ca.src[5] = Wv;    ca.dst[5] = wvbf;
    ca.src[6] = Wo;    ca.dst[6] = wobf;
    ca.mh = mh;
    cvt_all_kernel<<<7169, 256>>>(ca);

    // 2. merged Q/K/V projections
    big3_gemm<<<gBig3, 512, BIG_SMEM>>>(qbf, kbf, vbf, wqbf, wkbf, wvbf,
                                        qproj, kbhl, pk, vbhl);

    // 3. V transpose
    vt_kernel<<<dim3(PL/32, PDH/32, BH), dim3(32, 8)>>>(vbhl, vt);

    // 4. kv = K @ V^T (bf16) + column-mean -> mh
    kv_gemm<<<gKV, 256, BAT_SMEM>>>(kbhl, vbhl, kvbf, mh);

    // 5. fused attention (pipelined phases)
    fused_attn<<<gFA, 512, F23_SMEM>>>(qproj, kvbf, pk, vt, mh, attnbf, alpha, beta);

    // 6. o = attn @ Wo^T + bo
    bigo_gemm<<<gBigO, 512, BIG_SMEM>>>(attnbf, wobf, o, bo);

    // 7. residual + layernorm
    ln_kernel<<<PT, 256>>>(query, o, ln_g, ln_b, out);
}